// round 10
// baseline (speedup 1.0000x reference)
#include <cuda_runtime.h>
#include <cuda_bf16.h>
#include <math.h>
#include <stdint.h>

// Problem constants
#define BB   4
#define LSEQ 4096
#define HD   1024
#define UD   1024
#define U3   3072
#define NCHUNK 64
#define LC     64
#define KD   1024
#define KQ2  2048           // stored quantized K: [q1 | q2]
#define MROWS (BB*LSEQ)     // 16384

// Scratch (allocation-free: __device__ globals)
__device__ float g_rkv[(size_t)BB * LSEQ * U3];        // 192 MB fp32
__device__ float g_x[(size_t)BB * LSEQ * UD];          // 64 MB
__device__ float g_part[(size_t)BB * NCHUNK * 2 * UD]; // 2 MB
__device__ __align__(256) int8_t g_Aq[(size_t)MROWS * KQ2];   // 32 MB quant(inputs)
__device__ __align__(256) int8_t g_Xq[(size_t)MROWS * KQ2];   // 32 MB quant(x)
__device__ __align__(256) int8_t g_B1q[(size_t)U3 * KQ2];     //  6 MB quant+T(W_rkv)
__device__ __align__(256) int8_t g_B2q[(size_t)HD * KQ2];     //  2 MB quant+T(W_o)
__device__ float g_sA[MROWS];
__device__ float g_sX[MROWS];
__device__ float g_sB1[U3];
__device__ float g_sB2[HD];

__device__ __forceinline__ void cpa16(void* s, const void* g) {
    uint32_t sa = (uint32_t)__cvta_generic_to_shared(s);
    asm volatile("cp.async.cg.shared.global [%0], [%1], 16;" :: "r"(sa), "l"(g));
}

#define IMMA(d, a, b) \
    asm volatile( \
        "mma.sync.aligned.m16n8k32.row.col.s32.s8.s8.s32 " \
        "{%0,%1,%2,%3},{%4,%5,%6,%7},{%8,%9},{%0,%1,%2,%3};" \
        : "+r"(d[0]), "+r"(d[1]), "+r"(d[2]), "+r"(d[3]) \
        : "r"(a[0]), "r"(a[1]), "r"(a[2]), "r"(a[3]), "r"(b[0]), "r"(b[1]))

// ---------------------------------------------------------------------------
// int8 warp-MMA GEMM (mma.sync m16n8k32, s32 accum), 2-digit quantization:
//   C = sA*sB*(q1A.q1B + (q1A.q2B + q2A.q1B)/254) + bias
// 16 k64-chunks. CTA tile 128x64, 8 warps (4m x 2n), warp tile 32x32,
// 256 threads, 2 CTAs/SM. 2-stage cp.async pipeline, ldmatrix.x4 (b16 view).
// SMEM rows: 64 data bytes + 16 pad = 80B (16B-aligned, conflict-free).
// ---------------------------------------------------------------------------
#define RSB   80               // row stride (bytes)
#define ATILE (128 * RSB)      // 10240
#define BTILE (64 * RSB)       // 5120
#define STAGE (2 * ATILE + 2 * BTILE)   // 30720
#define SMEM_GEMM (2 * STAGE)  // 61440

__global__ void __launch_bounds__(256, 2) gemm_imma(
    const int8_t* __restrict__ A,
    const int8_t* __restrict__ Bt,
    const float* __restrict__ sA,
    const float* __restrict__ sB,
    const float* __restrict__ bias,
    float* __restrict__ C, int N)
{
    extern __shared__ int8_t smbuf[];
    const uint32_t smem0 = (uint32_t)__cvta_generic_to_shared(smbuf);

    const int tid  = threadIdx.x;
    const int m0   = blockIdx.y * 128;
    const int n0   = blockIdx.x * 64;
    const int warp = tid >> 5;
    const int lane = tid & 31;
    const int wm   = (warp >> 1) * 32;   // 0,32,64,96
    const int wn   = (warp & 1) * 32;    // 0 or 32
    const int gm   = lane >> 2;          // 0..7
    const int kq   = (lane & 3) * 2;     // 0,2,4,6

    // ldmatrix.x4 per-lane offsets (bytes, within one tile)
    const uint32_t aOff = (uint32_t)((wm + (lane & 7) + ((lane >> 3) & 1) * 8) * RSB
                                     + (lane >> 4) * 16);
    const uint32_t bOff = (uint32_t)((wn + (lane & 7) + ((lane >> 4) & 1) * 8) * RSB
                                     + ((lane >> 3) & 1) * 16);

    int acc1[2][4][4], acc2[2][4][4];
    #pragma unroll
    for (int i = 0; i < 2; i++)
        #pragma unroll
        for (int j = 0; j < 4; j++)
            #pragma unroll
            for (int t = 0; t < 4; t++) { acc1[i][j][t] = 0; acc2[i][j][t] = 0; }

    // loader: chunk ci (0..15, k64 each) -> stage st. 256 threads, 6 x 16B.
    const int lr = tid >> 2;        // 0..63 base row
    const int seg = (tid & 3) * 16; // 16B segment within 64B row-chunk
    auto load_chunk = [&](int ci, int st) {
        const size_t kof = (size_t)(ci << 6);
        int8_t* Aq1 = smbuf + (size_t)st * STAGE;
        int8_t* Aq2 = Aq1 + ATILE;
        int8_t* Bq1 = Aq2 + ATILE;
        int8_t* Bq2 = Bq1 + BTILE;
        #pragma unroll
        for (int h = 0; h < 2; h++) {
            int r = lr + h * 64;
            const int8_t* ga = A + (size_t)(m0 + r) * KQ2 + kof + seg;
            cpa16(Aq1 + r * RSB + seg, ga);
            cpa16(Aq2 + r * RSB + seg, ga + 1024);
        }
        {
            const int8_t* gb = Bt + (size_t)(n0 + lr) * KQ2 + kof + seg;
            cpa16(Bq1 + lr * RSB + seg, gb);
            cpa16(Bq2 + lr * RSB + seg, gb + 1024);
        }
        asm volatile("cp.async.commit_group;");
    };

    load_chunk(0, 0);

    const int NCH = 16;
    for (int ci = 0; ci < NCH; ci++) {
        const int st = ci & 1;
        asm volatile("cp.async.wait_group 0;" ::: "memory");
        __syncthreads();
        if (ci + 1 < NCH) load_chunk(ci + 1, st ^ 1);

        const uint32_t base   = smem0 + (uint32_t)st * STAGE;
        const uint32_t aBase1 = base + aOff;
        const uint32_t aBase2 = base + (uint32_t)ATILE + aOff;
        const uint32_t bBase1 = base + (uint32_t)(2 * ATILE) + bOff;
        const uint32_t bBase2 = base + (uint32_t)(2 * ATILE + BTILE) + bOff;

        #pragma unroll
        for (int kk = 0; kk < 2; kk++) {      // two k32 steps per k64 chunk
            uint32_t aq1[2][4], aq2[2][4], bf[4][2];
            #pragma unroll
            for (int i = 0; i < 2; i++)
                asm volatile(
                    "ldmatrix.sync.aligned.m8n8.x4.shared.b16 {%0,%1,%2,%3}, [%4];"
                    : "=r"(aq1[i][0]), "=r"(aq1[i][1]), "=r"(aq1[i][2]), "=r"(aq1[i][3])
                    : "r"(aBase1 + (uint32_t)(i * 16 * RSB + kk * 32)));
            #pragma unroll
            for (int i = 0; i < 2; i++)
                asm volatile(
                    "ldmatrix.sync.aligned.m8n8.x4.shared.b16 {%0,%1,%2,%3}, [%4];"
                    : "=r"(aq2[i][0]), "=r"(aq2[i][1]), "=r"(aq2[i][2]), "=r"(aq2[i][3])
                    : "r"(aBase2 + (uint32_t)(i * 16 * RSB + kk * 32)));
            // ---- B q1: acc1 += q1A*q1B ; acc2 += q2A*q1B ----
            #pragma unroll
            for (int j = 0; j < 2; j++)
                asm volatile(
                    "ldmatrix.sync.aligned.m8n8.x4.shared.b16 {%0,%1,%2,%3}, [%4];"
                    : "=r"(bf[2*j][0]), "=r"(bf[2*j][1]),
                      "=r"(bf[2*j+1][0]), "=r"(bf[2*j+1][1])
                    : "r"(bBase1 + (uint32_t)(j * 16 * RSB + kk * 32)));
            #pragma unroll
            for (int i = 0; i < 2; i++)
                #pragma unroll
                for (int j = 0; j < 4; j++) IMMA(acc1[i][j], aq1[i], bf[j]);
            #pragma unroll
            for (int i = 0; i < 2; i++)
                #pragma unroll
                for (int j = 0; j < 4; j++) IMMA(acc2[i][j], aq2[i], bf[j]);
            // ---- B q2: acc2 += q1A*q2B ----
            #pragma unroll
            for (int j = 0; j < 2; j++)
                asm volatile(
                    "ldmatrix.sync.aligned.m8n8.x4.shared.b16 {%0,%1,%2,%3}, [%4];"
                    : "=r"(bf[2*j][0]), "=r"(bf[2*j][1]),
                      "=r"(bf[2*j+1][0]), "=r"(bf[2*j+1][1])
                    : "r"(bBase2 + (uint32_t)(j * 16 * RSB + kk * 32)));
            #pragma unroll
            for (int i = 0; i < 2; i++)
                #pragma unroll
                for (int j = 0; j < 4; j++) IMMA(acc2[i][j], aq1[i], bf[j]);
        }
    }

    // Epilogue: dequant + bias + store
    const float inv254 = 1.0f / 254.0f;
    #pragma unroll
    for (int i = 0; i < 2; i++) {
        const int row = m0 + wm + i * 16 + gm;
        const float sa0 = sA[row], sa1 = sA[row + 8];
        #pragma unroll
        for (int j = 0; j < 4; j++) {
            const int col = n0 + wn + j * 8 + kq;
            const float sb0 = sB[col], sb1 = sB[col + 1];
            const float b0 = bias[col], b1 = bias[col + 1];
            float f0 = (float)acc1[i][j][0] + (float)acc2[i][j][0] * inv254;
            float f1 = (float)acc1[i][j][1] + (float)acc2[i][j][1] * inv254;
            float f2 = (float)acc1[i][j][2] + (float)acc2[i][j][2] * inv254;
            float f3 = (float)acc1[i][j][3] + (float)acc2[i][j][3] * inv254;
            float2 v0 = make_float2(f0 * sa0 * sb0 + b0, f1 * sa0 * sb1 + b1);
            float2 v1 = make_float2(f2 * sa1 * sb0 + b0, f3 * sa1 * sb1 + b1);
            *(float2*)&C[(size_t)row * N + col]       = v0;
            *(float2*)&C[(size_t)(row + 8) * N + col] = v1;
        }
    }
}

// ---------------------------------------------------------------------------
// Row quantization: X[R,1024] fp32 -> Q[R,2048] int8 ([q1|q2]), S[R] scale.
// One warp per row.
// ---------------------------------------------------------------------------
__global__ void __launch_bounds__(256) quant_rows(const float* __restrict__ X,
                                                  int8_t* __restrict__ Q,
                                                  float* __restrict__ S)
{
    const int row  = blockIdx.x * 8 + (threadIdx.x >> 5);
    const int lane = threadIdx.x & 31;
    float4 v[8];
    float m = 0.f;
    #pragma unroll
    for (int p = 0; p < 8; p++) {
        v[p] = ((const float4*)X)[(size_t)row * 256 + lane + 32 * p];
        m = fmaxf(m, fmaxf(fmaxf(fabsf(v[p].x), fabsf(v[p].y)),
                           fmaxf(fabsf(v[p].z), fabsf(v[p].w))));
    }
    #pragma unroll
    for (int off = 16; off; off >>= 1)
        m = fmaxf(m, __shfl_xor_sync(0xffffffffu, m, off));
    m = fmaxf(m, 1e-20f);
    const float inv = 127.0f / m;
    if (lane == 0) S[row] = m * (1.0f / 127.0f);
    #pragma unroll
    for (int p = 0; p < 8; p++) {
        float f[4] = { v[p].x, v[p].y, v[p].z, v[p].w };
        char q1[4], q2[4];
        #pragma unroll
        for (int e = 0; e < 4; e++) {
            float t  = f[e] * inv;
            float c1 = rintf(t);
            float c2 = rintf((t - c1) * 254.0f);
            q1[e] = (char)(int)c1;
            q2[e] = (char)(int)c2;
        }
        size_t o = (size_t)row * KQ2 + 4 * lane + 128 * p;
        *(char4*)&Q[o]        = make_char4(q1[0], q1[1], q1[2], q1[3]);
        *(char4*)&Q[o + 1024] = make_char4(q2[0], q2[1], q2[2], q2[3]);
    }
}

// ---------------------------------------------------------------------------
// Weight quantization + transpose: W[K,Ncols] fp32 -> Bt[n,2048] int8, S[n].
// One block per output column n.
// ---------------------------------------------------------------------------
__global__ void __launch_bounds__(256) quant_T(const float* __restrict__ W,
                                               int8_t* __restrict__ Bt,
                                               float* __restrict__ S, int Ncols)
{
    __shared__ float red[256];
    const int n   = blockIdx.x;
    const int tid = threadIdx.x;
    float vals[4];
    float m = 0.f;
    #pragma unroll
    for (int p = 0; p < 4; p++) {
        vals[p] = W[(size_t)(tid + 256 * p) * Ncols + n];
        m = fmaxf(m, fabsf(vals[p]));
    }
    red[tid] = m;
    __syncthreads();
    for (int s = 128; s; s >>= 1) {
        if (tid < s) red[tid] = fmaxf(red[tid], red[tid + s]);
        __syncthreads();
    }
    const float mm = fmaxf(red[0], 1e-20f);
    const float inv = 127.0f / mm;
    if (tid == 0) S[n] = mm * (1.0f / 127.0f);
    #pragma unroll
    for (int p = 0; p < 4; p++) {
        float t  = vals[p] * inv;
        float c1 = rintf(t);
        float c2 = rintf((t - c1) * 254.0f);
        size_t o = (size_t)n * KQ2 + tid + 256 * p;
        Bt[o]        = (int8_t)(int)c1;
        Bt[o + 1024] = (int8_t)(int)c2;
    }
}

// ---------------------------------------------------------------------------
// Chunked linear-recurrence scan (3 phases)
// ---------------------------------------------------------------------------
__global__ void __launch_bounds__(256) scan_phaseA(const float* __restrict__ nu_log)
{
    const int c = blockIdx.x * blockDim.x + threadIdx.x;
    const int chunk = blockIdx.y;
    const int b = blockIdx.z;
    const float lam = expf(-expf(nu_log[c]));

    size_t base = ((size_t)b * LSEQ + (size_t)chunk * LC) * U3;
    float y1 = 0.f, y2 = 0.f;
    #pragma unroll 4
    for (int i = 0; i < LC; i++) {
        size_t off = base + (size_t)i * U3;
        float kr = g_rkv[off + UD + c];
        float vr = g_rkv[off + 2 * UD + c];
        float kk = expf(kr);
        float kv = kk * vr;
        g_rkv[off + UD + c]     = kk;
        g_rkv[off + 2 * UD + c] = kv;
        y1 = fmaf(y1, lam, kv);
        y2 = fmaf(y2, lam, kk);
    }
    size_t p = (size_t)(b * NCHUNK + chunk) * 2 * UD + c;
    g_part[p]      = y1;
    g_part[p + UD] = y2;
}

__global__ void __launch_bounds__(256) scan_phaseB(const float* __restrict__ nu_log)
{
    const int c = blockIdx.x * blockDim.x + threadIdx.x;
    const int b = blockIdx.y;
    const float lam = expf(-expf(nu_log[c]));
    const float lamLc = powf(lam, (float)LC);
    float Y1 = 0.f, Y2 = 0.f;
    for (int j = 0; j < NCHUNK; j++) {
        size_t p = (size_t)(b * NCHUNK + j) * 2 * UD + c;
        float S1 = g_part[p], S2 = g_part[p + UD];
        g_part[p]      = Y1;
        g_part[p + UD] = Y2;
        Y1 = fmaf(Y1, lamLc, S1);
        Y2 = fmaf(Y2, lamLc, S2);
    }
}

__global__ void __launch_bounds__(256) scan_phaseC(const float* __restrict__ nu_log,
                                                   const float* __restrict__ gamma_log)
{
    const int c = blockIdx.x * blockDim.x + threadIdx.x;
    const int chunk = blockIdx.y;
    const int b = blockIdx.z;
    const float lam = expf(-expf(nu_log[c]));
    const float gamma = expf(nu_log[c] + gamma_log[c]) - 1.f;

    size_t p = (size_t)(b * NCHUNK + chunk) * 2 * UD + c;
    float y1 = g_part[p];
    float y2 = g_part[p + UD];

    size_t base  = ((size_t)b * LSEQ + (size_t)chunk * LC) * U3;
    size_t xbase = ((size_t)b * LSEQ + (size_t)chunk * LC) * UD;
    #pragma unroll 4
    for (int i = 0; i < LC; i++) {
        size_t off = base + (size_t)i * U3;
        float rr = g_rkv[off + c];
        float kk = g_rkv[off + UD + c];
        float kv = g_rkv[off + 2 * UD + c];
        y1 = fmaf(y1, lam, kv);
        y2 = fmaf(y2, lam, kk);
        float r = 1.f / (1.f + expf(-rr));
        float x = (y1 + gamma * kv) / (y2 + gamma * kk + 1e-6f) * r;
        g_x[xbase + (size_t)i * UD + c] = x;
    }
}

// ---------------------------------------------------------------------------
// Launch
// ---------------------------------------------------------------------------
extern "C" void kernel_launch(void* const* d_in, const int* in_sizes, int n_in,
                              void* d_out, int out_size)
{
    const float* inputs    = (const float*)d_in[0];
    const float* W_rkv     = (const float*)d_in[1];
    const float* b_rkv     = (const float*)d_in[2];
    const float* W_o       = (const float*)d_in[3];
    const float* b_o       = (const float*)d_in[4];
    const float* nu_log    = (const float*)d_in[5];
    const float* gamma_log = (const float*)d_in[6];
    float* out = (float*)d_out;

    float *p_rkv = nullptr, *p_x = nullptr;
    float *p_sA = nullptr, *p_sX = nullptr, *p_sB1 = nullptr, *p_sB2 = nullptr;
    int8_t *p_Aq = nullptr, *p_Xq = nullptr, *p_B1q = nullptr, *p_B2q = nullptr;
    cudaGetSymbolAddress((void**)&p_rkv, g_rkv);
    cudaGetSymbolAddress((void**)&p_x, g_x);
    cudaGetSymbolAddress((void**)&p_Aq, g_Aq);
    cudaGetSymbolAddress((void**)&p_Xq, g_Xq);
    cudaGetSymbolAddress((void**)&p_B1q, g_B1q);
    cudaGetSymbolAddress((void**)&p_B2q, g_B2q);
    cudaGetSymbolAddress((void**)&p_sA, g_sA);
    cudaGetSymbolAddress((void**)&p_sX, g_sX);
    cudaGetSymbolAddress((void**)&p_sB1, g_sB1);
    cudaGetSymbolAddress((void**)&p_sB2, g_sB2);

    static bool attr_set = false;
    if (!attr_set) {
        cudaFuncSetAttribute(gemm_imma, cudaFuncAttributeMaxDynamicSharedMemorySize, SMEM_GEMM);
        attr_set = true;
    }

    // Quantization (2-digit int8, per-row / per-output-column scales)
    quant_rows<<<MROWS / 8, 256>>>(inputs, p_Aq, p_sA);
    quant_T<<<U3, 256>>>(W_rkv, p_B1q, p_sB1, U3);
    quant_T<<<HD, 256>>>(W_o, p_B2q, p_sB2, HD);

    // GEMM1: rkv = inputs @ W_rkv + b_rkv   [16384, 3072]
    gemm_imma<<<dim3(U3 / 64, MROWS / 128), 256, SMEM_GEMM>>>(
        p_Aq, p_B1q, p_sA, p_sB1, b_rkv, p_rkv, U3);

    // Scan
    scan_phaseA<<<dim3(UD / 256, NCHUNK, BB), 256>>>(nu_log);
    scan_phaseB<<<dim3(UD / 256, BB), 256>>>(nu_log);
    scan_phaseC<<<dim3(UD / 256, NCHUNK, BB), 256>>>(nu_log, gamma_log);

    // GEMM2: out = x @ W_o + b_o   [16384, 1024]
    quant_rows<<<MROWS / 8, 256>>>(p_x, p_Xq, p_sX);
    gemm_imma<<<dim3(HD / 64, MROWS / 128), 256, SMEM_GEMM>>>(
        p_Xq, p_B2q, p_sX, p_sB2, b_o, out, HD);
}

// round 11
// speedup vs baseline: 3.3427x; 3.3427x over previous
#include <cuda_runtime.h>
#include <cuda_fp16.h>
#include <cuda_bf16.h>
#include <math.h>
#include <stdint.h>

// Problem constants
#define BB   4
#define LSEQ 4096
#define HD   1024
#define UD   1024
#define U3   3072
#define NCHUNK 64
#define LC     64
#define KH   1024           // A width (fp16, 1 digit)
#define KB2  2048           // B width (fp16, [hi | lo])
#define MROWS (BB*LSEQ)     // 16384

// Scratch (allocation-free: __device__ globals)
__device__ float g_rkv[(size_t)BB * LSEQ * U3];        // 192 MB fp32
__device__ float g_part[(size_t)BB * NCHUNK * 2 * UD]; // 2 MB
__device__ __half g_A16[(size_t)MROWS * KH];           // 32 MB fp16(inputs)
__device__ __half g_X16[(size_t)MROWS * KH];           // 32 MB fp16(x), written by scan
__device__ __half g_B1[(size_t)U3 * KB2];              // 12 MB split+T(W_rkv)
__device__ __half g_B2[(size_t)HD * KB2];              //  4 MB split+T(W_o)

__device__ __forceinline__ void cpa16(void* s, const void* g) {
    uint32_t sa = (uint32_t)__cvta_generic_to_shared(s);
    asm volatile("cp.async.cg.shared.global [%0], [%1], 16;" :: "r"(sa), "l"(g));
}

#define HMMA(d, a, b) \
    asm volatile( \
        "mma.sync.aligned.m16n8k16.row.col.f32.f16.f16.f32 " \
        "{%0,%1,%2,%3},{%4,%5,%6,%7},{%8,%9},{%0,%1,%2,%3};" \
        : "+f"(d[0]), "+f"(d[1]), "+f"(d[2]), "+f"(d[3]) \
        : "r"(a[0]), "r"(a[1]), "r"(a[2]), "r"(a[3]), "r"(b[0]), "r"(b[1]))

// ---------------------------------------------------------------------------
// fp16 warp-MMA GEMM (mma.sync m16n8k16, fp32 accum), 2-product scheme:
//   C = A*B_hi + A*B_lo + bias      (error ~= fp16 rounding of A only)
// 32 k32-chunks. CTA tile 128x128, 8 warps (4m x 2n), warp tile 32x64,
// 256 threads, 2 CTAs/SM. 2-stage cp.async pipeline, ldmatrix.x4, B-reg reuse.
// SMEM rows padded to 40 fp16 (80B): 16B-aligned, conflict-free ldmatrix.
// ---------------------------------------------------------------------------
#define RS    40                // row stride (fp16 elems)
#define TEL   (128 * RS)        // one tile (128 rows) elems
#define SEL   (3 * TEL)         // stage: A, Bhi, Blo
#define STB   (SEL * 2)         // bytes per stage (30720)
#define SMEM_GEMM (2 * STB)     // 61440 bytes

__global__ void __launch_bounds__(256, 2) gemm_mma(
    const __half* __restrict__ A,
    const __half* __restrict__ Bt,
    const float* __restrict__ bias,
    float* __restrict__ C, int N)
{
    extern __shared__ __half smbuf[];
    const uint32_t smem0 = (uint32_t)__cvta_generic_to_shared(smbuf);

    const int tid  = threadIdx.x;
    const int m0   = blockIdx.y * 128;
    const int n0   = blockIdx.x * 128;
    const int warp = tid >> 5;
    const int lane = tid & 31;
    const int wm   = (warp >> 1) * 32;   // 0,32,64,96
    const int wn   = (warp & 1) * 64;    // 0 or 64
    const int gm   = lane >> 2;          // 0..7
    const int kq   = (lane & 3) * 2;     // 0,2,4,6

    // ldmatrix.x4 per-lane offsets (bytes, within one tile)
    // A (m16 x k16): matrices ordered m-half, m-half+8, then k-half
    const uint32_t aOff = (uint32_t)(((wm + (lane & 7) + ((lane >> 3) & 1) * 8) * RS
                                      + (lane >> 4) * 8) * 2);
    // B (two n8 blocks x k16): matrices ordered k-half first, then n-half
    const uint32_t bOff = (uint32_t)(((wn + (lane & 7) + ((lane >> 4) & 1) * 8) * RS
                                      + ((lane >> 3) & 1) * 8) * 2);

    float acc[2][8][4];
    #pragma unroll
    for (int i = 0; i < 2; i++)
        #pragma unroll
        for (int j = 0; j < 8; j++)
            #pragma unroll
            for (int t = 0; t < 4; t++)
                acc[i][j][t] = 0.f;

    // loader: chunk ci (0..31, k32 each) -> stage st. 256 threads, 6 x 16B.
    const int lr = tid >> 2;        // 0..63 base row
    const int lj = (tid & 3) * 8;   // 16B segment within 64B row-chunk
    auto load_chunk = [&](int ci, int st) {
        const size_t kof = (size_t)(ci << 5);
        __half* As = smbuf + (size_t)st * SEL;
        __half* Bh = As + TEL;
        __half* Bl = Bh + TEL;
        #pragma unroll
        for (int h = 0; h < 2; h++) {
            int r = lr + h * 64;
            const __half* ga = A  + (size_t)(m0 + r) * KH  + kof + lj;
            const __half* gb = Bt + (size_t)(n0 + r) * KB2 + kof + lj;
            cpa16(As + r * RS + lj, ga);
            cpa16(Bh + r * RS + lj, gb);
            cpa16(Bl + r * RS + lj, gb + 1024);
        }
        asm volatile("cp.async.commit_group;");
    };

    load_chunk(0, 0);

    const int NCH = 32;
    for (int ci = 0; ci < NCH; ci++) {
        const int st = ci & 1;
        asm volatile("cp.async.wait_group 0;" ::: "memory");
        __syncthreads();
        if (ci + 1 < NCH) load_chunk(ci + 1, st ^ 1);

        const uint32_t base   = smem0 + (uint32_t)st * STB;
        const uint32_t aBase  = base + aOff;
        const uint32_t bBaseH = base + (uint32_t)(TEL * 2) + bOff;
        const uint32_t bBaseL = base + (uint32_t)(2 * TEL * 2) + bOff;

        #pragma unroll
        for (int kk = 0; kk < 2; kk++) {
            uint32_t af[2][4], bf[8][2];
            #pragma unroll
            for (int i = 0; i < 2; i++)
                asm volatile(
                    "ldmatrix.sync.aligned.m8n8.x4.shared.b16 {%0,%1,%2,%3}, [%4];"
                    : "=r"(af[i][0]), "=r"(af[i][1]), "=r"(af[i][2]), "=r"(af[i][3])
                    : "r"(aBase + (uint32_t)(i * 16 * RS * 2 + kk * 32)));
            // ---- B_hi: acc += A * B_hi ----
            #pragma unroll
            for (int j = 0; j < 4; j++)
                asm volatile(
                    "ldmatrix.sync.aligned.m8n8.x4.shared.b16 {%0,%1,%2,%3}, [%4];"
                    : "=r"(bf[2*j][0]), "=r"(bf[2*j][1]),
                      "=r"(bf[2*j+1][0]), "=r"(bf[2*j+1][1])
                    : "r"(bBaseH + (uint32_t)(j * 16 * RS * 2 + kk * 32)));
            #pragma unroll
            for (int i = 0; i < 2; i++)
                #pragma unroll
                for (int j = 0; j < 8; j++) HMMA(acc[i][j], af[i], bf[j]);
            // ---- B_lo: acc += A * B_lo (overwrites B_hi regs) ----
            #pragma unroll
            for (int j = 0; j < 4; j++)
                asm volatile(
                    "ldmatrix.sync.aligned.m8n8.x4.shared.b16 {%0,%1,%2,%3}, [%4];"
                    : "=r"(bf[2*j][0]), "=r"(bf[2*j][1]),
                      "=r"(bf[2*j+1][0]), "=r"(bf[2*j+1][1])
                    : "r"(bBaseL + (uint32_t)(j * 16 * RS * 2 + kk * 32)));
            #pragma unroll
            for (int i = 0; i < 2; i++)
                #pragma unroll
                for (int j = 0; j < 8; j++) HMMA(acc[i][j], af[i], bf[j]);
        }
    }

    // Epilogue: bias + store (float2 per fragment row)
    #pragma unroll
    for (int j = 0; j < 8; j++) {
        const int col = n0 + wn + j * 8 + kq;
        const float b0 = bias[col], b1 = bias[col + 1];
        #pragma unroll
        for (int i = 0; i < 2; i++) {
            const int row = m0 + wm + i * 16 + gm;
            float2 v0 = make_float2(acc[i][j][0] + b0, acc[i][j][1] + b1);
            float2 v1 = make_float2(acc[i][j][2] + b0, acc[i][j][3] + b1);
            *(float2*)&C[(size_t)row * N + col]       = v0;
            *(float2*)&C[(size_t)(row + 8) * N + col] = v1;
        }
    }
}

// ---------------------------------------------------------------------------
// fp32 -> fp16 cast, [R,1024] contiguous
// ---------------------------------------------------------------------------
__global__ void __launch_bounds__(256) tohalf_rows(const float* __restrict__ X,
                                                   __half* __restrict__ Y, int total4)
{
    int idx = blockIdx.x * 256 + threadIdx.x;
    if (idx >= total4) return;
    float4 v = ((const float4*)X)[idx];
    __half2 h0 = __floats2half2_rn(v.x, v.y);
    __half2 h1 = __floats2half2_rn(v.z, v.w);
    ((__half2*)Y)[idx * 2]     = h0;
    ((__half2*)Y)[idx * 2 + 1] = h1;
}

// ---------------------------------------------------------------------------
// W[K,Ncols] fp32 -> Bt[n,2048] fp16 ([hi|lo], transpose), tiled 32x32
// ---------------------------------------------------------------------------
__global__ void halfsplit_T(const float* __restrict__ W, __half* __restrict__ Bt,
                            int Ncols)
{
    __shared__ float t[32][33];
    int n = blockIdx.x * 32 + threadIdx.x;
    int k0 = blockIdx.y * 32;
    for (int i = threadIdx.y; i < 32; i += 8)
        t[i][threadIdx.x] = W[(size_t)(k0 + i) * Ncols + n];
    __syncthreads();
    int k = k0 + threadIdx.x;
    for (int i = threadIdx.y; i < 32; i += 8) {
        int nn = blockIdx.x * 32 + i;
        float v = t[threadIdx.x][i];
        __half h = __float2half_rn(v);
        __half l = __float2half_rn(v - __half2float(h));
        Bt[(size_t)nn * KB2 + k]        = h;
        Bt[(size_t)nn * KB2 + 1024 + k] = l;
    }
}

// ---------------------------------------------------------------------------
// Chunked linear-recurrence scan (3 phases); phase C emits fp16 x directly.
// ---------------------------------------------------------------------------
__global__ void __launch_bounds__(256) scan_phaseA(const float* __restrict__ nu_log)
{
    const int c = blockIdx.x * blockDim.x + threadIdx.x;
    const int chunk = blockIdx.y;
    const int b = blockIdx.z;
    const float lam = expf(-expf(nu_log[c]));

    size_t base = ((size_t)b * LSEQ + (size_t)chunk * LC) * U3;
    float y1 = 0.f, y2 = 0.f;
    #pragma unroll 4
    for (int i = 0; i < LC; i++) {
        size_t off = base + (size_t)i * U3;
        float kr = g_rkv[off + UD + c];
        float vr = g_rkv[off + 2 * UD + c];
        float kk = expf(kr);
        float kv = kk * vr;
        g_rkv[off + UD + c]     = kk;
        g_rkv[off + 2 * UD + c] = kv;
        y1 = fmaf(y1, lam, kv);
        y2 = fmaf(y2, lam, kk);
    }
    size_t p = (size_t)(b * NCHUNK + chunk) * 2 * UD + c;
    g_part[p]      = y1;
    g_part[p + UD] = y2;
}

__global__ void __launch_bounds__(256) scan_phaseB(const float* __restrict__ nu_log)
{
    const int c = blockIdx.x * blockDim.x + threadIdx.x;
    const int b = blockIdx.y;
    const float lam = expf(-expf(nu_log[c]));
    const float lamLc = powf(lam, (float)LC);
    float Y1 = 0.f, Y2 = 0.f;
    for (int j = 0; j < NCHUNK; j++) {
        size_t p = (size_t)(b * NCHUNK + j) * 2 * UD + c;
        float S1 = g_part[p], S2 = g_part[p + UD];
        g_part[p]      = Y1;
        g_part[p + UD] = Y2;
        Y1 = fmaf(Y1, lamLc, S1);
        Y2 = fmaf(Y2, lamLc, S2);
    }
}

__global__ void __launch_bounds__(256) scan_phaseC(const float* __restrict__ nu_log,
                                                   const float* __restrict__ gamma_log)
{
    const int c = blockIdx.x * blockDim.x + threadIdx.x;
    const int chunk = blockIdx.y;
    const int b = blockIdx.z;
    const float lam = expf(-expf(nu_log[c]));
    const float gamma = expf(nu_log[c] + gamma_log[c]) - 1.f;

    size_t p = (size_t)(b * NCHUNK + chunk) * 2 * UD + c;
    float y1 = g_part[p];
    float y2 = g_part[p + UD];

    size_t base  = ((size_t)b * LSEQ + (size_t)chunk * LC) * U3;
    size_t xbase = ((size_t)b * LSEQ + (size_t)chunk * LC) * UD;
    #pragma unroll 4
    for (int i = 0; i < LC; i++) {
        size_t off = base + (size_t)i * U3;
        float rr = g_rkv[off + c];
        float kk = g_rkv[off + UD + c];
        float kv = g_rkv[off + 2 * UD + c];
        y1 = fmaf(y1, lam, kv);
        y2 = fmaf(y2, lam, kk);
        float r = 1.f / (1.f + expf(-rr));
        float x = (y1 + gamma * kv) / (y2 + gamma * kk + 1e-6f) * r;
        g_X16[xbase + (size_t)i * UD + c] = __float2half_rn(x);
    }
}

// ---------------------------------------------------------------------------
// Launch
// ---------------------------------------------------------------------------
extern "C" void kernel_launch(void* const* d_in, const int* in_sizes, int n_in,
                              void* d_out, int out_size)
{
    const float* inputs    = (const float*)d_in[0];
    const float* W_rkv     = (const float*)d_in[1];
    const float* b_rkv     = (const float*)d_in[2];
    const float* W_o       = (const float*)d_in[3];
    const float* b_o       = (const float*)d_in[4];
    const float* nu_log    = (const float*)d_in[5];
    const float* gamma_log = (const float*)d_in[6];
    float* out = (float*)d_out;

    float *p_rkv = nullptr;
    __half *p_A16 = nullptr, *p_X16 = nullptr, *p_B1 = nullptr, *p_B2 = nullptr;
    cudaGetSymbolAddress((void**)&p_rkv, g_rkv);
    cudaGetSymbolAddress((void**)&p_A16, g_A16);
    cudaGetSymbolAddress((void**)&p_X16, g_X16);
    cudaGetSymbolAddress((void**)&p_B1, g_B1);
    cudaGetSymbolAddress((void**)&p_B2, g_B2);

    static bool attr_set = false;
    if (!attr_set) {
        cudaFuncSetAttribute(gemm_mma, cudaFuncAttributeMaxDynamicSharedMemorySize, SMEM_GEMM);
        attr_set = true;
    }

    // Operand conversion: A -> fp16; W -> fp16 2-digit [hi|lo], transposed
    tohalf_rows<<<(MROWS * 256 + 255) / 256, 256>>>(inputs, p_A16, MROWS * 256);
    halfsplit_T<<<dim3(U3 / 32, HD / 32), dim3(32, 8)>>>(W_rkv, p_B1, U3);
    halfsplit_T<<<dim3(HD / 32, UD / 32), dim3(32, 8)>>>(W_o, p_B2, HD);

    // GEMM1: rkv = inputs @ W_rkv + b_rkv   [16384, 3072]
    gemm_mma<<<dim3(U3 / 128, MROWS / 128), 256, SMEM_GEMM>>>(p_A16, p_B1, b_rkv, p_rkv, U3);

    // Scan (phase C writes x directly as fp16)
    scan_phaseA<<<dim3(UD / 256, NCHUNK, BB), 256>>>(nu_log);
    scan_phaseB<<<dim3(UD / 256, BB), 256>>>(nu_log);
    scan_phaseC<<<dim3(UD / 256, NCHUNK, BB), 256>>>(nu_log, gamma_log);

    // GEMM2: out = x @ W_o + b_o   [16384, 1024]
    gemm_mma<<<dim3(HD / 128, MROWS / 128), 256, SMEM_GEMM>>>(p_X16, p_B2, b_o, out, HD);
}

// round 12
// speedup vs baseline: 4.9960x; 1.4946x over previous
#include <cuda_runtime.h>
#include <cuda_fp16.h>
#include <math.h>
#include <stdint.h>

// Problem constants
#define BB   4
#define LSEQ 4096
#define HD   1024
#define UD   1024
#define U3   3072
#define NCHUNK 64
#define LC     64
#define KH   1024           // operand K width (fp16, single digit)
#define MROWS (BB*LSEQ)     // 16384

// Scratch (allocation-free: __device__ globals)
__device__ float g_rkv[(size_t)BB * LSEQ * U3];        // 192 MB fp32
__device__ float g_part[(size_t)BB * NCHUNK * 2 * UD]; // 2 MB
__device__ __half g_A16[(size_t)MROWS * KH];           // 32 MB fp16(inputs)
__device__ __half g_X16[(size_t)MROWS * KH];           // 32 MB fp16(x), written by scan
__device__ __half g_B1[(size_t)U3 * KH];               //  6 MB T(W_rkv) fp16
__device__ __half g_B2[(size_t)HD * KH];               //  2 MB T(W_o) fp16

__device__ __forceinline__ void cpa16(void* s, const void* g) {
    uint32_t sa = (uint32_t)__cvta_generic_to_shared(s);
    asm volatile("cp.async.cg.shared.global [%0], [%1], 16;" :: "r"(sa), "l"(g));
}

#define HMMA(d, a, b) \
    asm volatile( \
        "mma.sync.aligned.m16n8k16.row.col.f32.f16.f16.f32 " \
        "{%0,%1,%2,%3},{%4,%5,%6,%7},{%8,%9},{%0,%1,%2,%3};" \
        : "+f"(d[0]), "+f"(d[1]), "+f"(d[2]), "+f"(d[3]) \
        : "r"(a[0]), "r"(a[1]), "r"(a[2]), "r"(a[3]), "r"(b[0]), "r"(b[1]))

// ---------------------------------------------------------------------------
// fp16 warp-MMA GEMM (mma.sync m16n8k16, fp32 accum), single product:
//   C = A * B + bias    (fp16-rounded operands, fp32 accumulation)
// 32 k32-chunks. CTA tile 128x128, 8 warps (4m x 2n), warp tile 32x64,
// 256 threads, 2 CTAs/SM. 2-stage cp.async pipeline, ldmatrix.x4.
// SMEM rows padded to 40 fp16 (80B): 16B-aligned, conflict-free ldmatrix.
// ---------------------------------------------------------------------------
#define RS    40                // row stride (fp16 elems)
#define TEL   (128 * RS)        // one tile (128 rows) elems
#define SEL   (2 * TEL)         // stage: A, B
#define STB   (SEL * 2)         // bytes per stage (20480)
#define SMEM_GEMM (2 * STB)     // 40960 bytes

__global__ void __launch_bounds__(256, 2) gemm_mma(
    const __half* __restrict__ A,
    const __half* __restrict__ Bt,
    const float* __restrict__ bias,
    float* __restrict__ C, int N)
{
    extern __shared__ __half smbuf[];
    const uint32_t smem0 = (uint32_t)__cvta_generic_to_shared(smbuf);

    const int tid  = threadIdx.x;
    const int m0   = blockIdx.y * 128;
    const int n0   = blockIdx.x * 128;
    const int warp = tid >> 5;
    const int lane = tid & 31;
    const int wm   = (warp >> 1) * 32;   // 0,32,64,96
    const int wn   = (warp & 1) * 64;    // 0 or 64
    const int gm   = lane >> 2;          // 0..7
    const int kq   = (lane & 3) * 2;     // 0,2,4,6

    // ldmatrix.x4 per-lane offsets (bytes, within one tile)
    // A (m16 x k16): matrices ordered m-half, m-half+8, then k-half
    const uint32_t aOff = (uint32_t)(((wm + (lane & 7) + ((lane >> 3) & 1) * 8) * RS
                                      + (lane >> 4) * 8) * 2);
    // B (two n8 blocks x k16): matrices ordered k-half first, then n-half
    const uint32_t bOff = (uint32_t)(TEL * 2 +
                                     ((wn + (lane & 7) + ((lane >> 4) & 1) * 8) * RS
                                      + ((lane >> 3) & 1) * 8) * 2);

    float acc[2][8][4];
    #pragma unroll
    for (int i = 0; i < 2; i++)
        #pragma unroll
        for (int j = 0; j < 8; j++)
            #pragma unroll
            for (int t = 0; t < 4; t++)
                acc[i][j][t] = 0.f;

    // loader: chunk ci (0..31, k32 each) -> stage st. 256 threads, 4 x 16B.
    const int lr = tid >> 2;        // 0..63 base row
    const int lj = (tid & 3) * 8;   // 16B segment within 64B row-chunk
    auto load_chunk = [&](int ci, int st) {
        const size_t kof = (size_t)(ci << 5);
        __half* As = smbuf + (size_t)st * SEL;
        __half* Bs = As + TEL;
        #pragma unroll
        for (int h = 0; h < 2; h++) {
            int r = lr + h * 64;
            cpa16(As + r * RS + lj, A  + (size_t)(m0 + r) * KH + kof + lj);
            cpa16(Bs + r * RS + lj, Bt + (size_t)(n0 + r) * KH + kof + lj);
        }
        asm volatile("cp.async.commit_group;");
    };

    load_chunk(0, 0);

    const int NCH = 32;
    for (int ci = 0; ci < NCH; ci++) {
        const int st = ci & 1;
        asm volatile("cp.async.wait_group 0;" ::: "memory");
        __syncthreads();
        if (ci + 1 < NCH) load_chunk(ci + 1, st ^ 1);

        const uint32_t aBase = smem0 + (uint32_t)st * STB + aOff;
        const uint32_t bBase = smem0 + (uint32_t)st * STB + bOff;

        #pragma unroll
        for (int kk = 0; kk < 2; kk++) {
            uint32_t af[2][4], bf[8][2];
            #pragma unroll
            for (int i = 0; i < 2; i++)
                asm volatile(
                    "ldmatrix.sync.aligned.m8n8.x4.shared.b16 {%0,%1,%2,%3}, [%4];"
                    : "=r"(af[i][0]), "=r"(af[i][1]), "=r"(af[i][2]), "=r"(af[i][3])
                    : "r"(aBase + (uint32_t)(i * 16 * RS * 2 + kk * 32)));
            #pragma unroll
            for (int j = 0; j < 4; j++)
                asm volatile(
                    "ldmatrix.sync.aligned.m8n8.x4.shared.b16 {%0,%1,%2,%3}, [%4];"
                    : "=r"(bf[2*j][0]), "=r"(bf[2*j][1]),
                      "=r"(bf[2*j+1][0]), "=r"(bf[2*j+1][1])
                    : "r"(bBase + (uint32_t)(j * 16 * RS * 2 + kk * 32)));
            #pragma unroll
            for (int i = 0; i < 2; i++)
                #pragma unroll
                for (int j = 0; j < 8; j++) HMMA(acc[i][j], af[i], bf[j]);
        }
    }

    // Epilogue: bias + store (float2 per fragment row)
    #pragma unroll
    for (int j = 0; j < 8; j++) {
        const int col = n0 + wn + j * 8 + kq;
        const float b0 = bias[col], b1 = bias[col + 1];
        #pragma unroll
        for (int i = 0; i < 2; i++) {
            const int row = m0 + wm + i * 16 + gm;
            float2 v0 = make_float2(acc[i][j][0] + b0, acc[i][j][1] + b1);
            float2 v1 = make_float2(acc[i][j][2] + b0, acc[i][j][3] + b1);
            *(float2*)&C[(size_t)row * N + col]       = v0;
            *(float2*)&C[(size_t)(row + 8) * N + col] = v1;
        }
    }
}

// ---------------------------------------------------------------------------
// fp32 -> fp16 cast, [R,1024] contiguous
// ---------------------------------------------------------------------------
__global__ void __launch_bounds__(256) tohalf_rows(const float* __restrict__ X,
                                                   __half* __restrict__ Y, int total4)
{
    int idx = blockIdx.x * 256 + threadIdx.x;
    if (idx >= total4) return;
    float4 v = ((const float4*)X)[idx];
    __half2 h0 = __floats2half2_rn(v.x, v.y);
    __half2 h1 = __floats2half2_rn(v.z, v.w);
    ((__half2*)Y)[idx * 2]     = h0;
    ((__half2*)Y)[idx * 2 + 1] = h1;
}

// ---------------------------------------------------------------------------
// W[K,Ncols] fp32 -> Bt[n,1024] fp16 (transpose + cast), tiled 32x32
// ---------------------------------------------------------------------------
__global__ void halfcast_T(const float* __restrict__ W, __half* __restrict__ Bt,
                           int Ncols)
{
    __shared__ float t[32][33];
    int n = blockIdx.x * 32 + threadIdx.x;
    int k0 = blockIdx.y * 32;
    for (int i = threadIdx.y; i < 32; i += 8)
        t[i][threadIdx.x] = W[(size_t)(k0 + i) * Ncols + n];
    __syncthreads();
    int k = k0 + threadIdx.x;
    for (int i = threadIdx.y; i < 32; i += 8) {
        int nn = blockIdx.x * 32 + i;
        Bt[(size_t)nn * KH + k] = __float2half_rn(t[threadIdx.x][i]);
    }
}

// ---------------------------------------------------------------------------
// Chunked linear-recurrence scan (3 phases); phase C emits fp16 x directly.
// ---------------------------------------------------------------------------
__global__ void __launch_bounds__(256) scan_phaseA(const float* __restrict__ nu_log)
{
    const int c = blockIdx.x * blockDim.x + threadIdx.x;
    const int chunk = blockIdx.y;
    const int b = blockIdx.z;
    const float lam = expf(-expf(nu_log[c]));

    size_t base = ((size_t)b * LSEQ + (size_t)chunk * LC) * U3;
    float y1 = 0.f, y2 = 0.f;
    #pragma unroll 4
    for (int i = 0; i < LC; i++) {
        size_t off = base + (size_t)i * U3;
        float kr = g_rkv[off + UD + c];
        float vr = g_rkv[off + 2 * UD + c];
        float kk = expf(kr);
        float kv = kk * vr;
        g_rkv[off + UD + c]     = kk;
        g_rkv[off + 2 * UD + c] = kv;
        y1 = fmaf(y1, lam, kv);
        y2 = fmaf(y2, lam, kk);
    }
    size_t p = (size_t)(b * NCHUNK + chunk) * 2 * UD + c;
    g_part[p]      = y1;
    g_part[p + UD] = y2;
}

__global__ void __launch_bounds__(256) scan_phaseB(const float* __restrict__ nu_log)
{
    const int c = blockIdx.x * blockDim.x + threadIdx.x;
    const int b = blockIdx.y;
    const float lam = expf(-expf(nu_log[c]));
    const float lamLc = powf(lam, (float)LC);
    float Y1 = 0.f, Y2 = 0.f;
    for (int j = 0; j < NCHUNK; j++) {
        size_t p = (size_t)(b * NCHUNK + j) * 2 * UD + c;
        float S1 = g_part[p], S2 = g_part[p + UD];
        g_part[p]      = Y1;
        g_part[p + UD] = Y2;
        Y1 = fmaf(Y1, lamLc, S1);
        Y2 = fmaf(Y2, lamLc, S2);
    }
}

__global__ void __launch_bounds__(256) scan_phaseC(const float* __restrict__ nu_log,
                                                   const float* __restrict__ gamma_log)
{
    const int c = blockIdx.x * blockDim.x + threadIdx.x;
    const int chunk = blockIdx.y;
    const int b = blockIdx.z;
    const float lam = expf(-expf(nu_log[c]));
    const float gamma = expf(nu_log[c] + gamma_log[c]) - 1.f;

    size_t p = (size_t)(b * NCHUNK + chunk) * 2 * UD + c;
    float y1 = g_part[p];
    float y2 = g_part[p + UD];

    size_t base  = ((size_t)b * LSEQ + (size_t)chunk * LC) * U3;
    size_t xbase = ((size_t)b * LSEQ + (size_t)chunk * LC) * UD;
    #pragma unroll 4
    for (int i = 0; i < LC; i++) {
        size_t off = base + (size_t)i * U3;
        float rr = g_rkv[off + c];
        float kk = g_rkv[off + UD + c];
        float kv = g_rkv[off + 2 * UD + c];
        y1 = fmaf(y1, lam, kv);
        y2 = fmaf(y2, lam, kk);
        float r = 1.f / (1.f + expf(-rr));
        float x = (y1 + gamma * kv) / (y2 + gamma * kk + 1e-6f) * r;
        g_X16[xbase + (size_t)i * UD + c] = __float2half_rn(x);
    }
}

// ---------------------------------------------------------------------------
// Launch
// ---------------------------------------------------------------------------
extern "C" void kernel_launch(void* const* d_in, const int* in_sizes, int n_in,
                              void* d_out, int out_size)
{
    const float* inputs    = (const float*)d_in[0];
    const float* W_rkv     = (const float*)d_in[1];
    const float* b_rkv     = (const float*)d_in[2];
    const float* W_o       = (const float*)d_in[3];
    const float* b_o       = (const float*)d_in[4];
    const float* nu_log    = (const float*)d_in[5];
    const float* gamma_log = (const float*)d_in[6];
    float* out = (float*)d_out;

    float *p_rkv = nullptr;
    __half *p_A16 = nullptr, *p_X16 = nullptr, *p_B1 = nullptr, *p_B2 = nullptr;
    cudaGetSymbolAddress((void**)&p_rkv, g_rkv);
    cudaGetSymbolAddress((void**)&p_A16, g_A16);
    cudaGetSymbolAddress((void**)&p_X16, g_X16);
    cudaGetSymbolAddress((void**)&p_B1, g_B1);
    cudaGetSymbolAddress((void**)&p_B2, g_B2);

    static bool attr_set = false;
    if (!attr_set) {
        cudaFuncSetAttribute(gemm_mma, cudaFuncAttributeMaxDynamicSharedMemorySize, SMEM_GEMM);
        attr_set = true;
    }

    // Operand conversion: A -> fp16; W -> fp16, transposed
    tohalf_rows<<<(MROWS * 256 + 255) / 256, 256>>>(inputs, p_A16, MROWS * 256);
    halfcast_T<<<dim3(U3 / 32, HD / 32), dim3(32, 8)>>>(W_rkv, p_B1, U3);
    halfcast_T<<<dim3(HD / 32, UD / 32), dim3(32, 8)>>>(W_o, p_B2, HD);

    // GEMM1: rkv = inputs @ W_rkv + b_rkv   [16384, 3072]
    gemm_mma<<<dim3(U3 / 128, MROWS / 128), 256, SMEM_GEMM>>>(p_A16, p_B1, b_rkv, p_rkv, U3);

    // Scan (phase C writes x directly as fp16)
    scan_phaseA<<<dim3(UD / 256, NCHUNK, BB), 256>>>(nu_log);
    scan_phaseB<<<dim3(UD / 256, BB), 256>>>(nu_log);
    scan_phaseC<<<dim3(UD / 256, NCHUNK, BB), 256>>>(nu_log, gamma_log);

    // GEMM2: out = x @ W_o + b_o   [16384, 1024]
    gemm_mma<<<dim3(HD / 128, MROWS / 128), 256, SMEM_GEMM>>>(p_X16, p_B2, b_o, out, HD);
}

// round 13
// speedup vs baseline: 5.3230x; 1.0655x over previous
#include <cuda_runtime.h>
#include <cuda_fp16.h>
#include <math.h>
#include <stdint.h>

// Problem constants
#define BB   4
#define LSEQ 4096
#define HD   1024
#define UD   1024
#define U3   3072
#define NCHUNK 64
#define LC     64
#define KH   1024           // operand K width (fp16, single digit)
#define MROWS (BB*LSEQ)     // 16384

// Scratch (allocation-free: __device__ globals)
__device__ float g_rkv[(size_t)BB * LSEQ * U3];        // 192 MB fp32
__device__ float g_part[(size_t)BB * NCHUNK * 2 * UD]; // 2 MB
__device__ __half g_A16[(size_t)MROWS * KH];           // 32 MB fp16(inputs)
__device__ __half g_X16[(size_t)MROWS * KH];           // 32 MB fp16(x), written by scan
__device__ __half g_B1[(size_t)U3 * KH];               //  6 MB T(W_rkv) fp16
__device__ __half g_B2[(size_t)HD * KH];               //  2 MB T(W_o) fp16

__device__ __forceinline__ void cpa16(void* s, const void* g) {
    uint32_t sa = (uint32_t)__cvta_generic_to_shared(s);
    asm volatile("cp.async.cg.shared.global [%0], [%1], 16;" :: "r"(sa), "l"(g));
}

#define HMMA(d, a, b) \
    asm volatile( \
        "mma.sync.aligned.m16n8k16.row.col.f32.f16.f16.f32 " \
        "{%0,%1,%2,%3},{%4,%5,%6,%7},{%8,%9},{%0,%1,%2,%3};" \
        : "+f"(d[0]), "+f"(d[1]), "+f"(d[2]), "+f"(d[3]) \
        : "r"(a[0]), "r"(a[1]), "r"(a[2]), "r"(a[3]), "r"(b[0]), "r"(b[1]))

// ---------------------------------------------------------------------------
// fp16 warp-MMA GEMM (mma.sync m16n8k16, fp32 accum), single product:
//   C = A * B + bias
// 16 k64-chunks. CTA tile 128x128, 4 warps (2x2), warp tile 64x64,
// 128 threads, 2 CTAs/SM (R7-proven occupancy shape; 128 B/MMA LDSM).
// 2-stage cp.async pipeline (1 barrier/chunk), ldmatrix.x4.
// SMEM rows: 128B data + 16B pad = 144B (row i -> bank 9i = i mod 8; conflict-free).
// ---------------------------------------------------------------------------
#define RS    72                // row stride (fp16 elems) = 144 B
#define TEL   (128 * RS)        // one tile (128 rows) elems
#define SEL   (2 * TEL)         // stage: A, B
#define STB   (SEL * 2)         // bytes per stage (36864)
#define SMEM_GEMM (2 * STB)     // 73728 bytes

__global__ void __launch_bounds__(128, 2) gemm_mma(
    const __half* __restrict__ A,
    const __half* __restrict__ Bt,
    const float* __restrict__ bias,
    float* __restrict__ C, int N)
{
    extern __shared__ __half smbuf[];
    const uint32_t smem0 = (uint32_t)__cvta_generic_to_shared(smbuf);

    const int tid  = threadIdx.x;
    const int m0   = blockIdx.y * 128;
    const int n0   = blockIdx.x * 128;
    const int warp = tid >> 5;
    const int lane = tid & 31;
    const int wm   = (warp >> 1) * 64;   // 0 or 64
    const int wn   = (warp & 1) * 64;    // 0 or 64
    const int gm   = lane >> 2;          // 0..7
    const int kq   = (lane & 3) * 2;     // 0,2,4,6

    // ldmatrix.x4 per-lane offsets (bytes, within one tile)
    // A (m16 x k16): matrices ordered m-half, m-half+8, then k-half
    const uint32_t aOff = (uint32_t)(((wm + (lane & 7) + ((lane >> 3) & 1) * 8) * RS
                                      + (lane >> 4) * 8) * 2);
    // B (two n8 blocks x k16): matrices ordered k-half first, then n-half
    const uint32_t bOff = (uint32_t)(TEL * 2 +
                                     ((wn + (lane & 7) + ((lane >> 4) & 1) * 8) * RS
                                      + ((lane >> 3) & 1) * 8) * 2);

    float acc[4][8][4];
    #pragma unroll
    for (int i = 0; i < 4; i++)
        #pragma unroll
        for (int j = 0; j < 8; j++)
            #pragma unroll
            for (int t = 0; t < 4; t++)
                acc[i][j][t] = 0.f;

    // loader: chunk ci (0..15, k64 each) -> stage st. 128 threads, 16 x 16B.
    const int lr  = tid >> 3;       // 0..15 base row
    const int ljh = (tid & 7) * 8;  // 16B segment (in halves) within 128B row
    auto load_chunk = [&](int ci, int st) {
        const size_t kof = (size_t)(ci << 6);
        __half* As = smbuf + (size_t)st * SEL;
        __half* Bs = As + TEL;
        #pragma unroll
        for (int h = 0; h < 8; h++) {
            int r = lr + h * 16;
            cpa16(As + r * RS + ljh, A  + (size_t)(m0 + r) * KH + kof + ljh);
            cpa16(Bs + r * RS + ljh, Bt + (size_t)(n0 + r) * KH + kof + ljh);
        }
        asm volatile("cp.async.commit_group;");
    };

    load_chunk(0, 0);

    const int NCH = 16;
    for (int ci = 0; ci < NCH; ci++) {
        const int st = ci & 1;
        asm volatile("cp.async.wait_group 0;" ::: "memory");
        __syncthreads();
        if (ci + 1 < NCH) load_chunk(ci + 1, st ^ 1);

        const uint32_t aBase = smem0 + (uint32_t)st * STB + aOff;
        const uint32_t bBase = smem0 + (uint32_t)st * STB + bOff;

        #pragma unroll
        for (int kk = 0; kk < 4; kk++) {           // four k16 steps per k64
            uint32_t af[4][4], bf[8][2];
            #pragma unroll
            for (int i = 0; i < 4; i++)
                asm volatile(
                    "ldmatrix.sync.aligned.m8n8.x4.shared.b16 {%0,%1,%2,%3}, [%4];"
                    : "=r"(af[i][0]), "=r"(af[i][1]), "=r"(af[i][2]), "=r"(af[i][3])
                    : "r"(aBase + (uint32_t)(i * 16 * RS * 2 + kk * 32)));
            #pragma unroll
            for (int j = 0; j < 4; j++)
                asm volatile(
                    "ldmatrix.sync.aligned.m8n8.x4.shared.b16 {%0,%1,%2,%3}, [%4];"
                    : "=r"(bf[2*j][0]), "=r"(bf[2*j][1]),
                      "=r"(bf[2*j+1][0]), "=r"(bf[2*j+1][1])
                    : "r"(bBase + (uint32_t)(j * 16 * RS * 2 + kk * 32)));
            #pragma unroll
            for (int i = 0; i < 4; i++)
                #pragma unroll
                for (int j = 0; j < 8; j++) HMMA(acc[i][j], af[i], bf[j]);
        }
    }

    // Epilogue: bias + store (float2 per fragment row)
    #pragma unroll
    for (int j = 0; j < 8; j++) {
        const int col = n0 + wn + j * 8 + kq;
        const float b0 = bias[col], b1 = bias[col + 1];
        #pragma unroll
        for (int i = 0; i < 4; i++) {
            const int row = m0 + wm + i * 16 + gm;
            float2 v0 = make_float2(acc[i][j][0] + b0, acc[i][j][1] + b1);
            float2 v1 = make_float2(acc[i][j][2] + b0, acc[i][j][3] + b1);
            *(float2*)&C[(size_t)row * N + col]       = v0;
            *(float2*)&C[(size_t)(row + 8) * N + col] = v1;
        }
    }
}

// ---------------------------------------------------------------------------
// fp32 -> fp16 cast, [R,1024] contiguous
// ---------------------------------------------------------------------------
__global__ void __launch_bounds__(256) tohalf_rows(const float* __restrict__ X,
                                                   __half* __restrict__ Y, int total4)
{
    int idx = blockIdx.x * 256 + threadIdx.x;
    if (idx >= total4) return;
    float4 v = ((const float4*)X)[idx];
    __half2 h0 = __floats2half2_rn(v.x, v.y);
    __half2 h1 = __floats2half2_rn(v.z, v.w);
    ((__half2*)Y)[idx * 2]     = h0;
    ((__half2*)Y)[idx * 2 + 1] = h1;
}

// ---------------------------------------------------------------------------
// W[K,Ncols] fp32 -> Bt[n,1024] fp16 (transpose + cast), tiled 32x32
// ---------------------------------------------------------------------------
__global__ void halfcast_T(const float* __restrict__ W, __half* __restrict__ Bt,
                           int Ncols)
{
    __shared__ float t[32][33];
    int n = blockIdx.x * 32 + threadIdx.x;
    int k0 = blockIdx.y * 32;
    for (int i = threadIdx.y; i < 32; i += 8)
        t[i][threadIdx.x] = W[(size_t)(k0 + i) * Ncols + n];
    __syncthreads();
    int k = k0 + threadIdx.x;
    for (int i = threadIdx.y; i < 32; i += 8) {
        int nn = blockIdx.x * 32 + i;
        Bt[(size_t)nn * KH + k] = __float2half_rn(t[threadIdx.x][i]);
    }
}

// ---------------------------------------------------------------------------
// Chunked linear-recurrence scan (3 phases); phase C emits fp16 x directly.
// ---------------------------------------------------------------------------
__global__ void __launch_bounds__(256) scan_phaseA(const float* __restrict__ nu_log)
{
    const int c = blockIdx.x * blockDim.x + threadIdx.x;
    const int chunk = blockIdx.y;
    const int b = blockIdx.z;
    const float lam = expf(-expf(nu_log[c]));

    size_t base = ((size_t)b * LSEQ + (size_t)chunk * LC) * U3;
    float y1 = 0.f, y2 = 0.f;
    #pragma unroll 4
    for (int i = 0; i < LC; i++) {
        size_t off = base + (size_t)i * U3;
        float kr = g_rkv[off + UD + c];
        float vr = g_rkv[off + 2 * UD + c];
        float kk = expf(kr);
        float kv = kk * vr;
        g_rkv[off + UD + c]     = kk;
        g_rkv[off + 2 * UD + c] = kv;
        y1 = fmaf(y1, lam, kv);
        y2 = fmaf(y2, lam, kk);
    }
    size_t p = (size_t)(b * NCHUNK + chunk) * 2 * UD + c;
    g_part[p]      = y1;
    g_part[p + UD] = y2;
}

__global__ void __launch_bounds__(256) scan_phaseB(const float* __restrict__ nu_log)
{
    const int c = blockIdx.x * blockDim.x + threadIdx.x;
    const int b = blockIdx.y;
    const float lam = expf(-expf(nu_log[c]));
    const float lamLc = powf(lam, (float)LC);
    float Y1 = 0.f, Y2 = 0.f;
    for (int j = 0; j < NCHUNK; j++) {
        size_t p = (size_t)(b * NCHUNK + j) * 2 * UD + c;
        float S1 = g_part[p], S2 = g_part[p + UD];
        g_part[p]      = Y1;
        g_part[p + UD] = Y2;
        Y1 = fmaf(Y1, lamLc, S1);
        Y2 = fmaf(Y2, lamLc, S2);
    }
}

__global__ void __launch_bounds__(256) scan_phaseC(const float* __restrict__ nu_log,
                                                   const float* __restrict__ gamma_log)
{
    const int c = blockIdx.x * blockDim.x + threadIdx.x;
    const int chunk = blockIdx.y;
    const int b = blockIdx.z;
    const float lam = expf(-expf(nu_log[c]));
    const float gamma = expf(nu_log[c] + gamma_log[c]) - 1.f;

    size_t p = (size_t)(b * NCHUNK + chunk) * 2 * UD + c;
    float y1 = g_part[p];
    float y2 = g_part[p + UD];

    size_t base  = ((size_t)b * LSEQ + (size_t)chunk * LC) * U3;
    size_t xbase = ((size_t)b * LSEQ + (size_t)chunk * LC) * UD;
    #pragma unroll 4
    for (int i = 0; i < LC; i++) {
        size_t off = base + (size_t)i * U3;
        float rr = g_rkv[off + c];
        float kk = g_rkv[off + UD + c];
        float kv = g_rkv[off + 2 * UD + c];
        y1 = fmaf(y1, lam, kv);
        y2 = fmaf(y2, lam, kk);
        float r = 1.f / (1.f + expf(-rr));
        float x = (y1 + gamma * kv) / (y2 + gamma * kk + 1e-6f) * r;
        g_X16[xbase + (size_t)i * UD + c] = __float2half_rn(x);
    }
}

// ---------------------------------------------------------------------------
// Launch
// ---------------------------------------------------------------------------
extern "C" void kernel_launch(void* const* d_in, const int* in_sizes, int n_in,
                              void* d_out, int out_size)
{
    const float* inputs    = (const float*)d_in[0];
    const float* W_rkv     = (const float*)d_in[1];
    const float* b_rkv     = (const float*)d_in[2];
    const float* W_o       = (const float*)d_in[3];
    const float* b_o       = (const float*)d_in[4];
    const float* nu_log    = (const float*)d_in[5];
    const float* gamma_log = (const float*)d_in[6];
    float* out = (float*)d_out;

    float *p_rkv = nullptr;
    __half *p_A16 = nullptr, *p_X16 = nullptr, *p_B1 = nullptr, *p_B2 = nullptr;
    cudaGetSymbolAddress((void**)&p_rkv, g_rkv);
    cudaGetSymbolAddress((void**)&p_A16, g_A16);
    cudaGetSymbolAddress((void**)&p_X16, g_X16);
    cudaGetSymbolAddress((void**)&p_B1, g_B1);
    cudaGetSymbolAddress((void**)&p_B2, g_B2);

    static bool attr_set = false;
    if (!attr_set) {
        cudaFuncSetAttribute(gemm_mma, cudaFuncAttributeMaxDynamicSharedMemorySize, SMEM_GEMM);
        attr_set = true;
    }

    // Operand conversion: A -> fp16; W -> fp16, transposed
    tohalf_rows<<<(MROWS * 256 + 255) / 256, 256>>>(inputs, p_A16, MROWS * 256);
    halfcast_T<<<dim3(U3 / 32, HD / 32), dim3(32, 8)>>>(W_rkv, p_B1, U3);
    halfcast_T<<<dim3(HD / 32, UD / 32), dim3(32, 8)>>>(W_o, p_B2, HD);

    // GEMM1: rkv = inputs @ W_rkv + b_rkv   [16384, 3072]
    gemm_mma<<<dim3(U3 / 128, MROWS / 128), 128, SMEM_GEMM>>>(p_A16, p_B1, b_rkv, p_rkv, U3);

    // Scan (phase C writes x directly as fp16)
    scan_phaseA<<<dim3(UD / 256, NCHUNK, BB), 256>>>(nu_log);
    scan_phaseB<<<dim3(UD / 256, BB), 256>>>(nu_log);
    scan_phaseC<<<dim3(UD / 256, NCHUNK, BB), 256>>>(nu_log, gamma_log);

    // GEMM2: out = x @ W_o + b_o   [16384, 1024]
    gemm_mma<<<dim3(HD / 128, MROWS / 128), 128, SMEM_GEMM>>>(p_X16, p_B2, b_o, out, HD);
}